// round 14
// baseline (speedup 1.0000x reference)
#include <cuda_runtime.h>
#include <cuda_bf16.h>
#include <math.h>
#include <stdint.h>

#define B_   4
#define N_   4096
#define DIMM 1024
#define HEADS 16
#define HD   64
#define ROWS (B_*N_)          // 16384
#define NBH  (B_*HEADS)       // 64

// ---------------- scratch (device globals: allocation-free) ----------------
__device__ __nv_bfloat16 g_Qh[(size_t)NBH * N_ * HD];   // featurized q/k/v bf16 splits
__device__ __nv_bfloat16 g_Ql[(size_t)NBH * N_ * HD];
__device__ __nv_bfloat16 g_Kh[(size_t)NBH * N_ * HD];
__device__ __nv_bfloat16 g_Kl[(size_t)NBH * N_ * HD];
__device__ __nv_bfloat16 g_Vh[(size_t)NBH * N_ * HD];
__device__ __nv_bfloat16 g_Vl[(size_t)NBH * N_ * HD];
__device__ __nv_bfloat16 g_xh [(size_t)ROWS * DIMM];    // x split
__device__ __nv_bfloat16 g_xl [(size_t)ROWS * DIMM];
__device__ __nv_bfloat16 g_ah [(size_t)ROWS * DIMM];    // attn split (linattn out)
__device__ __nv_bfloat16 g_al [(size_t)ROWS * DIMM];
__device__ __nv_bfloat16 g_wqh[(size_t)3 * DIMM * DIMM]; // wqkv^T split [N][K]
__device__ __nv_bfloat16 g_wql[(size_t)3 * DIMM * DIMM];
__device__ __nv_bfloat16 g_woh[(size_t)DIMM * DIMM];     // wout^T split
__device__ __nv_bfloat16 g_wol[(size_t)DIMM * DIMM];
__device__ float2 g_rope[(size_t)N_ * 32];               // (cos,sin) per (n,d2) 1MB

// ---------------- helpers ----------------------------------------------------
__device__ __forceinline__ uint32_t smem_u32(const void* p) {
    uint32_t a;
    asm("{ .reg .u64 t; cvta.to.shared.u64 t, %1; cvt.u32.u64 %0, t; }"
        : "=r"(a) : "l"(p));
    return a;
}
__device__ __forceinline__ void cp16(uint32_t s, const void* g) {
    asm volatile("cp.async.cg.shared.global [%0], [%1], 16;" :: "r"(s), "l"(g));
}
#define CP_COMMIT() asm volatile("cp.async.commit_group;" ::: "memory")
#define CP_WAIT(n)  asm volatile("cp.async.wait_group %0;" :: "n"(n) : "memory")
#define LDSM4(r0, r1, r2, r3, addr) asm volatile( \
    "ldmatrix.sync.aligned.m8n8.x4.shared.b16 {%0,%1,%2,%3}, [%4];" \
    : "=r"(r0), "=r"(r1), "=r"(r2), "=r"(r3) : "r"(addr))
__device__ __forceinline__ void mma16816(float* c, const uint32_t* a,
                                         const uint32_t* b) {
    asm volatile(
        "mma.sync.aligned.m16n8k16.row.col.f32.bf16.bf16.f32 "
        "{%0,%1,%2,%3}, {%4,%5,%6,%7}, {%8,%9}, {%0,%1,%2,%3};"
        : "+f"(c[0]), "+f"(c[1]), "+f"(c[2]), "+f"(c[3])
        : "r"(a[0]), "r"(a[1]), "r"(a[2]), "r"(a[3]), "r"(b[0]), "r"(b[1]));
}
// 64B-row swizzle (GEMM stage tiles, V half tiles); ck in 0..3
__device__ __forceinline__ uint32_t swz(int r, int ck) {
    return (uint32_t)(((r >> 1) << 7) |
                      ((((((r & 1) << 2) | ck)) ^ ((r >> 1) & 7)) << 4));
}
// 128B-row swizzle (attention 64-col tiles); ck in 0..7
#define SWZ64(r, ck) ((uint32_t)((r) * 128 + ((((ck) ^ ((r) & 7))) << 4)))

__device__ __forceinline__ float bfu(unsigned short u) {
    return __bfloat162float(__ushort_as_bfloat16(u));
}
__device__ __forceinline__ void split2u(float v, unsigned short& hh,
                                        unsigned short& ll) {
    __nv_bfloat16 b = __float2bfloat16(v);
    hh = __bfloat16_as_ushort(b);
    ll = __bfloat16_as_ushort(__float2bfloat16(v - __bfloat162float(b)));
}

// ---------------- rope table: (cos,sin) for all (n, d2) ---------------------
__global__ void rope_table(float2* __restrict__ t) {
    int i = blockIdx.x * blockDim.x + threadIdx.x;
    if (i >= N_ * 32) return;
    int d2 = i & 31, n = i >> 5;
    float inv = powf(10000.f, -(float)d2 * (1.f / 32.f));
    float ang = (float)n * inv;
    t[i] = make_float2(cosf(ang), sinf(ang));
}

// ---------------- split fp32 -> bf16 hi/lo ----------------------------------
__global__ void split_bf16(const float* __restrict__ in,
                           __nv_bfloat16* __restrict__ hi,
                           __nv_bfloat16* __restrict__ lo, int n4) {
    int i = blockIdx.x * blockDim.x + threadIdx.x;
    if (i >= n4) return;
    float4 v = ((const float4*)in)[i];
    unsigned short h0, l0, h1, l1, h2, l2, h3, l3;
    split2u(v.x, h0, l0); split2u(v.y, h1, l1);
    split2u(v.z, h2, l2); split2u(v.w, h3, l3);
    ((ushort4*)hi)[i] = make_ushort4(h0, h1, h2, h3);
    ((ushort4*)lo)[i] = make_ushort4(l0, l1, l2, l3);
}

// ---------------- transpose + split: w[K][N] -> wt_hi/lo [N][K] --------------
__global__ void transpose_split(const float* __restrict__ w,
                                __nv_bfloat16* __restrict__ th,
                                __nv_bfloat16* __restrict__ tl, int K, int N) {
    __shared__ float t[32][33];
    int tx = threadIdx.x, ty = threadIdx.y;
    int x = blockIdx.x * 32 + tx;
#pragma unroll
    for (int j = 0; j < 32; j += 8) {
        int y = blockIdx.y * 32 + ty + j;
        t[ty + j][tx] = w[(size_t)y * N + x];
    }
    __syncthreads();
#pragma unroll
    for (int j = 0; j < 32; j += 8) {
        int n = blockIdx.x * 32 + ty + j;
        int k = blockIdx.y * 32 + tx;
        float v = t[tx][ty + j];
        __nv_bfloat16 h = __float2bfloat16(v);
        th[(size_t)n * K + k] = h;
        tl[(size_t)n * K + k] = __float2bfloat16(v - __bfloat162float(h));
    }
}

// ---------------- split-bf16 tensor-core GEMM core (3-stage cp.async) --------
#define STAGE    32768
#define OFFS_AH  0
#define OFFS_AL  8192
#define OFFS_BH  16384
#define OFFS_BL  24576
#define GEMM_SMEM (3 * STAGE)

#define GEMM_LOAD_STAGE(bs, kk)                                               \
    do {                                                                      \
        size_t a0 = (size_t)(m0 + lr0) * K + (kk) + lc0 * 8;                  \
        size_t a1 = (size_t)(m0 + lr1) * K + (kk) + lc1 * 8;                  \
        size_t b0 = (size_t)(n0 + lr0) * K + (kk) + lc0 * 8;                  \
        size_t b1 = (size_t)(n0 + lr1) * K + (kk) + lc1 * 8;                  \
        cp16((bs) + OFFS_AH + so0, Ah + a0); cp16((bs) + OFFS_AH + so1, Ah + a1); \
        cp16((bs) + OFFS_AL + so0, Al + a0); cp16((bs) + OFFS_AL + so1, Al + a1); \
        cp16((bs) + OFFS_BH + so0, Bh + b0); cp16((bs) + OFFS_BH + so1, Bh + b1); \
        cp16((bs) + OFFS_BL + so0, Bl + b0); cp16((bs) + OFFS_BL + so1, Bl + b1); \
    } while (0)

#define GEMM_MAINLOOP()                                                       \
    float acc[4][4][4];                                                       \
    _Pragma("unroll")                                                         \
    for (int a = 0; a < 4; a++)                                               \
        _Pragma("unroll")                                                     \
        for (int b = 0; b < 4; b++)                                           \
            _Pragma("unroll")                                                 \
            for (int c = 0; c < 4; c++) acc[a][b][c] = 0.f;                   \
    const int nIter = K >> 5;                                                 \
    GEMM_LOAD_STAGE(sb, 0); CP_COMMIT();                                      \
    GEMM_LOAD_STAGE(sb + STAGE, 32); CP_COMMIT();                             \
    for (int it = 0; it < nIter; it++) {                                      \
        if (it == nIter - 1) { CP_WAIT(0); } else { CP_WAIT(1); }             \
        __syncthreads();                                                      \
        if (it + 2 < nIter) {                                                 \
            uint32_t bs = sb + ((it + 2) % 3) * STAGE;                        \
            GEMM_LOAD_STAGE(bs, (it + 2) << 5);                               \
            CP_COMMIT();                                                      \
        }                                                                     \
        const uint32_t ss = sb + (it % 3) * STAGE;                            \
        _Pragma("unroll")                                                     \
        for (int ks = 0; ks < 2; ks++) {                                      \
            const uint32_t kx = ks * 32;                                      \
            uint32_t bhf[4][2], blf[4][2];                                    \
            _Pragma("unroll")                                                 \
            for (int p = 0; p < 2; p++) {                                     \
                uint32_t r0, r1, r2, r3;                                      \
                LDSM4(r0, r1, r2, r3, ss + OFFS_BH + (baseB[p] ^ kx));        \
                bhf[2 * p][0] = r0; bhf[2 * p][1] = r1;                       \
                bhf[2 * p + 1][0] = r2; bhf[2 * p + 1][1] = r3;               \
                LDSM4(r0, r1, r2, r3, ss + OFFS_BL + (baseB[p] ^ kx));        \
                blf[2 * p][0] = r0; blf[2 * p][1] = r1;                       \
                blf[2 * p + 1][0] = r2; blf[2 * p + 1][1] = r3;               \
            }                                                                 \
            _Pragma("unroll")                                                 \
            for (int mf = 0; mf < 4; mf++) {                                  \
                uint32_t ahf[4], alf[4];                                      \
                LDSM4(ahf[0], ahf[1], ahf[2], ahf[3], ss + OFFS_AH + (baseA[mf] ^ kx)); \
                LDSM4(alf[0], alf[1], alf[2], alf[3], ss + OFFS_AL + (baseA[mf] ^ kx)); \
                _Pragma("unroll")                                             \
                for (int nf = 0; nf < 4; nf++) {                              \
                    mma16816(acc[mf][nf], ahf, bhf[nf]);                      \
                    mma16816(acc[mf][nf], ahf, blf[nf]);                      \
                    mma16816(acc[mf][nf], alf, bhf[nf]);                      \
                }                                                             \
            }                                                                 \
        }                                                                     \
    }

#define GEMM_PREAMBLE()                                                       \
    extern __shared__ char sm[];                                              \
    const uint32_t sb = smem_u32(sm);                                         \
    const int tid = threadIdx.x;                                              \
    const int lane = tid & 31, wid = tid >> 5;                                \
    const int warp_m = wid & 1, warp_n = wid >> 1;                            \
    const int m0 = blockIdx.y * 128, n0 = blockIdx.x * 128;                   \
    const int i0 = tid, i1 = tid + 256;                                       \
    const int lr0 = i0 >> 2, lc0 = i0 & 3;                                    \
    const int lr1 = i1 >> 2, lc1 = i1 & 3;                                    \
    const uint32_t so0 = swz(lr0, lc0), so1 = swz(lr1, lc1);                  \
    uint32_t baseA[4], baseB[2];                                              \
    _Pragma("unroll")                                                         \
    for (int mf = 0; mf < 4; mf++)                                            \
        baseA[mf] = swz(warp_m * 64 + mf * 16 + (lane & 15), lane >> 4);      \
    _Pragma("unroll")                                                         \
    for (int p = 0; p < 2; p++)                                               \
        baseB[p] = swz(warp_n * 32 + p * 16 + ((lane >> 4) << 3) + (lane & 7),\
                       (lane >> 3) & 1);

// generic GEMM: C fp32 out
__global__ void __launch_bounds__(256, 2) mma_gemm(
    const __nv_bfloat16* __restrict__ Ah, const __nv_bfloat16* __restrict__ Al,
    const __nv_bfloat16* __restrict__ Bh, const __nv_bfloat16* __restrict__ Bl,
    float* __restrict__ C, int M, int N, int K) {
    GEMM_PREAMBLE();
    GEMM_MAINLOOP();
#pragma unroll
    for (int mf = 0; mf < 4; mf++) {
#pragma unroll
        for (int nf = 0; nf < 4; nf++) {
            int row = m0 + warp_m * 64 + mf * 16 + (lane >> 2);
            int col = n0 + warp_n * 32 + nf * 8 + 2 * (lane & 3);
            *(float2*)(C + (size_t)row * N + col) =
                make_float2(acc[mf][nf][0], acc[mf][nf][1]);
            *(float2*)(C + (size_t)(row + 8) * N + col) =
                make_float2(acc[mf][nf][2], acc[mf][nf][3]);
        }
    }
}

// GEMM1 with fused RoPE(table) + ELU + bf16 hi/lo split epilogue (N = 3072)
__global__ void __launch_bounds__(256, 2) mma_gemm_rope(
    const __nv_bfloat16* __restrict__ Ah, const __nv_bfloat16* __restrict__ Al,
    const __nv_bfloat16* __restrict__ Bh, const __nv_bfloat16* __restrict__ Bl,
    __nv_bfloat16* __restrict__ Qh, __nv_bfloat16* __restrict__ Ql,
    __nv_bfloat16* __restrict__ Kh, __nv_bfloat16* __restrict__ Kl,
    __nv_bfloat16* __restrict__ Vh, __nv_bfloat16* __restrict__ Vl,
    const float2* __restrict__ rt, int K) {
    GEMM_PREAMBLE();
    GEMM_MAINLOOP();
    // stage tile to smem (fp32, stride 132)
    __syncthreads();
    float* stage = (float*)sm;
#pragma unroll
    for (int mf = 0; mf < 4; mf++) {
#pragma unroll
        for (int nf = 0; nf < 4; nf++) {
            int row = warp_m * 64 + mf * 16 + (lane >> 2);
            int col = warp_n * 32 + nf * 8 + 2 * (lane & 3);
            stage[row * 132 + col]     = acc[mf][nf][0];
            stage[row * 132 + col + 1] = acc[mf][nf][1];
            stage[(row + 8) * 132 + col]     = acc[mf][nf][2];
            stage[(row + 8) * 132 + col + 1] = acc[mf][nf][3];
        }
    }
    __syncthreads();
    const int section = n0 >> 10;        // 0=Q 1=K 2=V
    const int hbase = (n0 & 1023) >> 6;  // first head in tile
    unsigned short* dh = (unsigned short*)(section == 0 ? Qh : (section == 1 ? Kh : Vh));
    unsigned short* dl = (unsigned short*)(section == 0 ? Ql : (section == 1 ? Kl : Vl));
    const float SC = 0.35355339059327373f;
    for (int i = tid; i < 8192; i += 256) {
        int r = i >> 6, hh = (i >> 5) & 1, d2 = i & 31;
        float v1 = stage[r * 132 + hh * 64 + d2];
        float v2 = stage[r * 132 + hh * 64 + d2 + 32];
        int gr = m0 + r, bI = gr >> 12, n = gr & 4095;
        size_t ob = ((size_t)(bI * HEADS + hbase + hh) * N_ + n) * HD;
        unsigned short hA, lA, hB, lB;
        if (section < 2) {
            float2 csn = rt[n * 32 + d2];
            float r1 = v1 * csn.x - v2 * csn.y, r2 = v1 * csn.y + v2 * csn.x;
            float y1 = r1 * SC; float f1 = (y1 > 0.f) ? y1 + 1.f : __expf(y1);
            float y2 = r2 * SC; float f2 = (y2 > 0.f) ? y2 + 1.f : __expf(y2);
            split2u(f1, hA, lA); split2u(f2, hB, lB);
        } else {
            split2u(v1, hA, lA); split2u(v2, hB, lB);
        }
        dh[ob + d2] = hA;      dl[ob + d2] = lA;
        dh[ob + d2 + 32] = hB; dl[ob + d2 + 32] = lB;
    }
}

// ---------------- mma-based chunked linear attention, m-split x2 -------------
#define T_QH 0
#define T_QL 8192
#define T_KH 16384
#define T_KL 24576
#define T_VH 32768                 // 64x32 half tile (64B rows), 4096 B
#define T_VL 36864
#define BUFSZ 40960
#define O_KTH (2*BUFSZ)            // 81920  (64x64 SWZ64)
#define O_KTL (O_KTH + 8192)
#define O_VTH (O_KTL + 8192)       // 98304  (32x64 SWZ64, 4096 B)
#define O_VTL (O_VTH + 4096)
#define O_SH  (O_VTL + 4096)       // 106496 (64x64 SWZ64)
#define O_SL  (O_SH + 8192)
#define O_KVH (O_SL + 8192)        // 122880 (32x64 SWZ64, 4096 B)
#define O_KVL (O_KVH + 4096)
#define O_KVF (O_KVL + 4096)       // 131072 (fp32 32x64 = 8192 B)
#define O_KS  (O_KVF + 8192)       // 139264
#define O_DEN (O_KS + 256)
#define O_DENP (O_DEN + 256)
#define LA_SMEM (O_DENP + 1024)    // 140800

__device__ __forceinline__ void mm64(uint32_t aHt, uint32_t aLt,
                                     uint32_t bHt, uint32_t bLt,
                                     float (*acc)[2][4], int wm, int wn, int lane) {
    const uint32_t aOff0 = SWZ64(wm * 32 + (lane & 15), (lane >> 4));
    const uint32_t aOff1 = SWZ64(wm * 32 + 16 + (lane & 15), (lane >> 4));
    const uint32_t bOff  = SWZ64(wn * 16 + ((lane >> 4) << 3) + (lane & 7),
                                 (lane >> 3) & 1);
#pragma unroll
    for (int kx = 0; kx < 4; kx++) {
        const uint32_t x = kx << 5;
        uint32_t BH[2][2], BL[2][2], r0, r1, r2, r3;
        LDSM4(r0, r1, r2, r3, bHt + (bOff ^ x));
        BH[0][0] = r0; BH[0][1] = r1; BH[1][0] = r2; BH[1][1] = r3;
        LDSM4(r0, r1, r2, r3, bLt + (bOff ^ x));
        BL[0][0] = r0; BL[0][1] = r1; BL[1][0] = r2; BL[1][1] = r3;
#pragma unroll
        for (int mf = 0; mf < 2; mf++) {
            uint32_t ao = (mf ? aOff1 : aOff0) ^ x;
            uint32_t AH[4], AL[4];
            LDSM4(AH[0], AH[1], AH[2], AH[3], aHt + ao);
            LDSM4(AL[0], AL[1], AL[2], AL[3], aLt + ao);
#pragma unroll
            for (int nf = 0; nf < 2; nf++) {
                mma16816(acc[mf][nf], AH, BH[nf]);
                mma16816(acc[mf][nf], AH, BL[nf]);
                mma16816(acc[mf][nf], AL, BH[nf]);
            }
        }
    }
}

__device__ __forceinline__ void mm16(uint32_t aHt, uint32_t aLt,
                                     uint32_t bHt, uint32_t bLt,
                                     float (*acc)[4], int ar, int bc, int lane) {
    const uint32_t aOff = SWZ64(ar + (lane & 15), (lane >> 4));
    const uint32_t bOff = SWZ64(bc + ((lane >> 4) << 3) + (lane & 7),
                                (lane >> 3) & 1);
#pragma unroll
    for (int kx = 0; kx < 4; kx++) {
        const uint32_t x = kx << 5;
        uint32_t BH[2][2], BL[2][2], r0, r1, r2, r3;
        LDSM4(r0, r1, r2, r3, bHt + (bOff ^ x));
        BH[0][0] = r0; BH[0][1] = r1; BH[1][0] = r2; BH[1][1] = r3;
        LDSM4(r0, r1, r2, r3, bLt + (bOff ^ x));
        BL[0][0] = r0; BL[0][1] = r1; BL[1][0] = r2; BL[1][1] = r3;
        uint32_t AH[4], AL[4];
        LDSM4(AH[0], AH[1], AH[2], AH[3], aHt + (aOff ^ x));
        LDSM4(AL[0], AL[1], AL[2], AL[3], aLt + (aOff ^ x));
#pragma unroll
        for (int nf = 0; nf < 2; nf++) {
            mma16816(acc[nf], AH, BH[nf]);
            mma16816(acc[nf], AH, BL[nf]);
            mma16816(acc[nf], AL, BH[nf]);
        }
    }
}

__device__ __forceinline__ void load_tile64(uint32_t dst,
                                            const __nv_bfloat16* g,
                                            size_t rowbase, int tid) {
#pragma unroll
    for (int uu = 0; uu < 2; uu++) {
        int u = tid + uu * 256;
        int r = u >> 3, ck = u & 7;
        cp16(dst + SWZ64(r, ck), g + rowbase + r * 64 + ck * 8);
    }
}
__device__ __forceinline__ void load_vhalf(uint32_t dst,
                                           const __nv_bfloat16* g,
                                           size_t rowbase, int mh, int tid) {
    int r = tid >> 2, ck = tid & 3;
    cp16(dst + swz(r, ck), g + rowbase + r * 64 + mh * 32 + ck * 8);
}

__global__ void __launch_bounds__(256) linattn_mma(
    const __nv_bfloat16* __restrict__ Qh, const __nv_bfloat16* __restrict__ Ql,
    const __nv_bfloat16* __restrict__ Kh, const __nv_bfloat16* __restrict__ Kl,
    const __nv_bfloat16* __restrict__ Vh, const __nv_bfloat16* __restrict__ Vl,
    __nv_bfloat16* __restrict__ ah, __nv_bfloat16* __restrict__ al) {
    extern __shared__ __align__(128) char smx[];
    const uint32_t sb = smem_u32(smx);
    const int tid = threadIdx.x;
    const int lane = tid & 31, wid = tid >> 5;
    const int wm = wid & 1, wn = wid >> 1;          // P1 geometry (2x4)
    const int wr3 = (wid & 3) * 16, wc3 = (wid >> 2) * 16;  // P3: 64x32
    const int wr4 = (wid & 1) * 16, wc4 = (wid >> 1) * 16;  // P4: 32x64
    const int bh = blockIdx.x >> 1;
    const int mh = blockIdx.x & 1;
    const int bIdx = bh >> 4, hIdx = bh & 15;
    const size_t gb = (size_t)bh * N_ * HD;

    float* ksp  = (float*)(smx + O_KS);
    float* denp = (float*)(smx + O_DENP);
    float* denv = (float*)(smx + O_DEN);
    float* kvf  = (float*)(smx + O_KVF);

    for (int i = tid; i < 2048; i += 256) {
        kvf[i] = 0.f;
        *(unsigned short*)(smx + O_KVH + i * 2) = 0;
        *(unsigned short*)(smx + O_KVL + i * 2) = 0;
    }
    if (tid < 64) ksp[tid] = 0.f;

    load_tile64(sb + T_QH, Qh, gb, tid);
    load_tile64(sb + T_QL, Ql, gb, tid);
    load_tile64(sb + T_KH, Kh, gb, tid);
    load_tile64(sb + T_KL, Kl, gb, tid);
    load_vhalf(sb + T_VH, Vh, gb, mh, tid);
    load_vhalf(sb + T_VL, Vl, gb, mh, tid);
    CP_COMMIT();
    __syncthreads();

    for (int ch = 0; ch < 64; ch++) {
        const int n0 = ch * 64;
        const uint32_t bo = (ch & 1) * BUFSZ;
        CP_WAIT(0);
        __syncthreads();

        for (int idx = tid; idx < 4096; idx += 256) {
            int i = idx >> 6, d = idx & 63;
            uint32_t ro = SWZ64(i, d >> 3) + (d & 7) * 2;
            uint32_t wo = SWZ64(d, i >> 3) + (i & 7) * 2;
            *(unsigned short*)(smx + O_KTH + wo) = *(unsigned short*)(smx + bo + T_KH + ro);
            *(unsigned short*)(smx + O_KTL + wo) = *(unsigned short*)(smx + bo + T_KL + ro);
        }
        for (int idx = tid; idx < 2048; idx += 256) {
            int m = idx >> 6, i = idx & 63;
            uint32_t ro = swz(i, m >> 3) + (m & 7) * 2;
            uint32_t wo = SWZ64(m, i >> 3) + (i & 7) * 2;
            *(unsigned short*)(smx + O_VTH + wo) = *(unsigned short*)(smx + bo + T_VH + ro);
            *(unsigned short*)(smx + O_VTL + wo) = *(unsigned short*)(smx + bo + T_VL + ro);
        }
        if (ch + 1 < 64) {
            const uint32_t bo2 = ((ch + 1) & 1) * BUFSZ;
            size_t rb = gb + (size_t)(n0 + 64) * HD;
            load_tile64(sb + bo2 + T_QH, Qh, rb, tid);
            load_tile64(sb + bo2 + T_QL, Ql, rb, tid);
            load_tile64(sb + bo2 + T_KH, Kh, rb, tid);
            load_tile64(sb + bo2 + T_KL, Kl, rb, tid);
            load_vhalf(sb + bo2 + T_VH, Vh, rb, mh, tid);
            load_vhalf(sb + bo2 + T_VL, Vl, rb, mh, tid);
            CP_COMMIT();
        }
        __syncthreads();

        // ---- P1: S = Q K^T, mask, rowsums, split to smem ----
        {
            float accS[2][2][4];
#pragma unroll
            for (int a = 0; a < 2; a++)
#pragma unroll
                for (int b = 0; b < 2; b++)
#pragma unroll
                    for (int e = 0; e < 4; e++) accS[a][b][e] = 0.f;
            mm64(sb + bo + T_QH, sb + bo + T_QL, sb + bo + T_KH, sb + bo + T_KL,
                 accS, wm, wn, lane);
#pragma unroll
            for (int mf = 0; mf < 2; mf++) {
                int r0 = wm * 32 + mf * 16 + (lane >> 2), r1 = r0 + 8;
                float rs0 = 0.f, rs1 = 0.f;
#pragma unroll
                for (int nf = 0; nf < 2; nf++) {
                    int cc = wn * 16 + nf * 8 + 2 * (lane & 3);
                    float a0 = (cc     <= r0) ? accS[mf][nf][0] : 0.f;
                    float a1 = (cc + 1 <= r0) ? accS[mf][nf][1] : 0.f;
                    float a2 = (cc     <= r1) ? accS[mf][nf][2] : 0.f;
                    float a3 = (cc + 1 <= r1) ? accS[mf][nf][3] : 0.f;
                    rs0 += a0 + a1; rs1 += a2 + a3;
                    unsigned short h0, l0, h1, l1;
                    split2u(a0, h0, l0); split2u(a1, h1, l1);
                    uint32_t so = SWZ64(r0, cc >> 3) + (cc & 7) * 2;
                    *(ushort2*)(smx + O_SH + so) = make_ushort2(h0, h1);
                    *(ushort2*)(smx + O_SL + so) = make_ushort2(l0, l1);
                    split2u(a2, h0, l0); split2u(a3, h1, l1);
                    so = SWZ64(r1, cc >> 3) + (cc & 7) * 2;
                    *(ushort2*)(smx + O_SH + so) = make_ushort2(h0, h1);
                    *(ushort2*)(smx + O_SL + so) = make_ushort2(l0, l1);
                }
                rs0 += __shfl_xor_sync(0xffffffffu, rs0, 1);
                rs0 += __shfl_xor_sync(0xffffffffu, rs0, 2);
                rs1 += __shfl_xor_sync(0xffffffffu, rs1, 1);
                rs1 += __shfl_xor_sync(0xffffffffu, rs1, 2);
                if ((lane & 3) == 0) {
                    denp[wn * 64 + r0] = rs0;
                    denp[wn * 64 + r1] = rs1;
                }
            }
        }
        __syncthreads();

        // ---- P2: den ----
        if (tid < 64) {
            int i = tid;
            float s = denp[i] + denp[64 + i] + denp[128 + i] + denp[192 + i];
            for (int d = 0; d < 64; d++) {
                uint32_t qo = SWZ64(i, d >> 3) + (d & 7) * 2;
                float qv = bfu(*(unsigned short*)(smx + bo + T_QH + qo)) +
                           bfu(*(unsigned short*)(smx + bo + T_QL + qo));
                s += qv * ksp[d];
            }
            denv[i] = fmaxf(s, 1e-6f);
        }
        __syncthreads();

        // ---- P3: O(64x32) ----
        {
            float accO[2][4];
#pragma unroll
            for (int b = 0; b < 2; b++)
#pragma unroll
                for (int e = 0; e < 4; e++) accO[b][e] = 0.f;
            mm16(sb + bo + T_QH, sb + bo + T_QL, sb + O_KVH, sb + O_KVL,
                 accO, wr3, wc3, lane);
            mm16(sb + O_SH, sb + O_SL, sb + O_VTH, sb + O_VTL,
                 accO, wr3, wc3, lane);
            int r0 = wr3 + (lane >> 2), r1 = r0 + 8;
            float i0 = 1.f / denv[r0], i1 = 1.f / denv[r1];
#pragma unroll
            for (int nf = 0; nf < 2; nf++) {
                int cc = wc3 + nf * 8 + 2 * (lane & 3);
                unsigned short h0, l0, h1, l1;
                size_t ro = (size_t)(bIdx * N_ + n0 + r0) * DIMM + hIdx * 64 +
                            mh * 32 + cc;
                split2u(accO[nf][0] * i0, h0, l0);
                split2u(accO[nf][1] * i0, h1, l1);
                *(ushort2*)((unsigned short*)ah + ro) = make_ushort2(h0, h1);
                *(ushort2*)((unsigned short*)al + ro) = make_ushort2(l0, l1);
                ro = (size_t)(bIdx * N_ + n0 + r1) * DIMM + hIdx * 64 +
                     mh * 32 + cc;
                split2u(accO[nf][2] * i1, h0, l0);
                split2u(accO[nf][3] * i1, h1, l1);
                *(ushort2*)((unsigned short*)ah + ro) = make_ushort2(h0, h1);
                *(ushort2*)((unsigned short*)al + ro) = make_ushort2(l0, l1);
            }
        }

        // ---- P4: KVt += V^T K ----
        {
            float accU[2][4];
#pragma unroll
            for (int b = 0; b < 2; b++)
#pragma unroll
                for (int e = 0; e < 4; e++) accU[b][e] = 0.f;
            mm16(sb + O_VTH, sb + O_VTL, sb + O_KTH, sb + O_KTL,
                 accU, wr4, wc4, lane);
            int m0r = wr4 + (lane >> 2), m1r = m0r + 8;
#pragma unroll
            for (int nf = 0; nf < 2; nf++) {
                int dd = wc4 + nf * 8 + 2 * (lane & 3);
                kvf[m0r * 64 + dd]     += accU[nf][0];
                kvf[m0r * 64 + dd + 1] += accU[nf][1];
                kvf[m1r * 64 + dd]     += accU[nf][2];
                kvf[m1r * 64 + dd + 1] += accU[nf][3];
            }
        }
        __syncthreads();
        for (int idx = tid; idx < 2048; idx += 256) {
            int m = idx >> 6, d = idx & 63;
            unsigned short hh, ll;
            split2u(kvf[idx], hh, ll);
            uint32_t o = SWZ64(m, d >> 3) + (d & 7) * 2;
            *(unsigned short*)(smx + O_KVH + o) = hh;
            *(unsigned short*)(smx + O_KVL + o) = ll;
        }
        if (tid < 64) {
            int d = tid;
            float s = ksp[d];
            for (int i2 = 0; i2 < 64; i2++) {
                uint32_t o = SWZ64(d, i2 >> 3) + (i2 & 7) * 2;
                s += bfu(*(unsigned short*)(smx + O_KTH + o)) +
                     bfu(*(unsigned short*)(smx + O_KTL + o));
            }
            ksp[d] = s;
        }
        __syncthreads();
    }
}

// ---------------- launch -----------------------------------------------------
extern "C" void kernel_launch(void* const* d_in, const int* in_sizes, int n_in,
                              void* d_out, int out_size) {
    const float* x    = (const float*)d_in[0];
    const float* wqkv = (const float*)d_in[1];
    const float* wout = (const float*)d_in[2];
    float* out = (float*)d_out;

    __nv_bfloat16 *Qh, *Ql, *Kh, *Kl, *Vh, *Vl;
    __nv_bfloat16 *xh, *xl, *ah, *al, *wqh, *wql, *woh, *wol;
    float2* rt;
    cudaGetSymbolAddress((void**)&Qh,  g_Qh);
    cudaGetSymbolAddress((void**)&Ql,  g_Ql);
    cudaGetSymbolAddress((void**)&Kh,  g_Kh);
    cudaGetSymbolAddress((void**)&Kl,  g_Kl);
    cudaGetSymbolAddress((void**)&Vh,  g_Vh);
    cudaGetSymbolAddress((void**)&Vl,  g_Vl);
    cudaGetSymbolAddress((void**)&xh,  g_xh);
    cudaGetSymbolAddress((void**)&xl,  g_xl);
    cudaGetSymbolAddress((void**)&ah,  g_ah);
    cudaGetSymbolAddress((void**)&al,  g_al);
    cudaGetSymbolAddress((void**)&wqh, g_wqh);
    cudaGetSymbolAddress((void**)&wql, g_wql);
    cudaGetSymbolAddress((void**)&woh, g_woh);
    cudaGetSymbolAddress((void**)&wol, g_wol);
    cudaGetSymbolAddress((void**)&rt,  g_rope);

    cudaFuncSetAttribute(mma_gemm, cudaFuncAttributeMaxDynamicSharedMemorySize,
                         GEMM_SMEM);
    cudaFuncSetAttribute(mma_gemm_rope,
                         cudaFuncAttributeMaxDynamicSharedMemorySize, GEMM_SMEM);
    cudaFuncSetAttribute(linattn_mma, cudaFuncAttributeMaxDynamicSharedMemorySize,
                         LA_SMEM);

    // rope table; split x; transpose+split weights
    {
        rope_table<<<(N_ * 32 + 255) / 256, 256>>>(rt);
        int n4 = ROWS * DIMM / 4;
        split_bf16<<<(n4 + 255) / 256, 256>>>(x, xh, xl, n4);
        transpose_split<<<dim3(3 * DIMM / 32, DIMM / 32), dim3(32, 8)>>>(
            wqkv, wqh, wql, DIMM, 3 * DIMM);
        transpose_split<<<dim3(DIMM / 32, DIMM / 32), dim3(32, 8)>>>(
            wout, woh, wol, DIMM, DIMM);
    }
    // 1) qkv = x @ w_qkv with fused RoPE(table)+ELU+split epilogue
    mma_gemm_rope<<<dim3(3 * DIMM / 128, ROWS / 128), 256, GEMM_SMEM>>>(
        xh, xl, wqh, wql, Qh, Ql, Kh, Kl, Vh, Vl, rt, DIMM);
    // 2) tensor-core chunked linear attention, m-split x2
    linattn_mma<<<NBH * 2, 256, LA_SMEM>>>(Qh, Ql, Kh, Kl, Vh, Vl, ah, al);
    // 3) out = attn @ w_out
    mma_gemm<<<dim3(DIMM / 128, ROWS / 128), 256, GEMM_SMEM>>>(
        ah, al, woh, wol, out, ROWS, DIMM, DIMM);
}

// round 15
// speedup vs baseline: 1.0581x; 1.0581x over previous
#include <cuda_runtime.h>
#include <cuda_bf16.h>
#include <math.h>
#include <stdint.h>

#define B_   4
#define N_   4096
#define DIMM 1024
#define HEADS 16
#define HD   64
#define ROWS (B_*N_)          // 16384
#define NBH  (B_*HEADS)       // 64

// ---------------- scratch (device globals: allocation-free) ----------------
__device__ float g_qkv[(size_t)ROWS * 3 * DIMM];        // qkv fp32
__device__ __nv_bfloat16 g_Qh[(size_t)NBH * N_ * HD];   // featurized q/k/v bf16 splits
__device__ __nv_bfloat16 g_Ql[(size_t)NBH * N_ * HD];
__device__ __nv_bfloat16 g_Kh[(size_t)NBH * N_ * HD];
__device__ __nv_bfloat16 g_Kl[(size_t)NBH * N_ * HD];
__device__ __nv_bfloat16 g_Vh[(size_t)NBH * N_ * HD];
__device__ __nv_bfloat16 g_Vl[(size_t)NBH * N_ * HD];
__device__ __nv_bfloat16 g_xh [(size_t)ROWS * DIMM];    // x split
__device__ __nv_bfloat16 g_xl [(size_t)ROWS * DIMM];
__device__ __nv_bfloat16 g_ah [(size_t)ROWS * DIMM];    // attn split (linattn out)
__device__ __nv_bfloat16 g_al [(size_t)ROWS * DIMM];
__device__ __nv_bfloat16 g_wqh[(size_t)3 * DIMM * DIMM]; // wqkv^T split [N][K]
__device__ __nv_bfloat16 g_wql[(size_t)3 * DIMM * DIMM];
__device__ __nv_bfloat16 g_woh[(size_t)DIMM * DIMM];     // wout^T split
__device__ __nv_bfloat16 g_wol[(size_t)DIMM * DIMM];
__device__ float2 g_rope[(size_t)N_ * 32];               // (cos,sin) per (n,d2) 1MB

// ---------------- helpers ----------------------------------------------------
__device__ __forceinline__ uint32_t smem_u32(const void* p) {
    uint32_t a;
    asm("{ .reg .u64 t; cvta.to.shared.u64 t, %1; cvt.u32.u64 %0, t; }"
        : "=r"(a) : "l"(p));
    return a;
}
__device__ __forceinline__ void cp16(uint32_t s, const void* g) {
    asm volatile("cp.async.cg.shared.global [%0], [%1], 16;" :: "r"(s), "l"(g));
}
#define CP_COMMIT() asm volatile("cp.async.commit_group;" ::: "memory")
#define CP_WAIT(n)  asm volatile("cp.async.wait_group %0;" :: "n"(n) : "memory")
#define LDSM4(r0, r1, r2, r3, addr) asm volatile( \
    "ldmatrix.sync.aligned.m8n8.x4.shared.b16 {%0,%1,%2,%3}, [%4];" \
    : "=r"(r0), "=r"(r1), "=r"(r2), "=r"(r3) : "r"(addr))
__device__ __forceinline__ void mma16816(float* c, const uint32_t* a,
                                         const uint32_t* b) {
    asm volatile(
        "mma.sync.aligned.m16n8k16.row.col.f32.bf16.bf16.f32 "
        "{%0,%1,%2,%3}, {%4,%5,%6,%7}, {%8,%9}, {%0,%1,%2,%3};"
        : "+f"(c[0]), "+f"(c[1]), "+f"(c[2]), "+f"(c[3])
        : "r"(a[0]), "r"(a[1]), "r"(a[2]), "r"(a[3]), "r"(b[0]), "r"(b[1]));
}
// 64B-row swizzle (GEMM stage tiles, V half tiles); ck in 0..3
__device__ __forceinline__ uint32_t swz(int r, int ck) {
    return (uint32_t)(((r >> 1) << 7) |
                      ((((((r & 1) << 2) | ck)) ^ ((r >> 1) & 7)) << 4));
}
// 128B-row swizzle (attention 64-col tiles); ck in 0..7
#define SWZ64(r, ck) ((uint32_t)((r) * 128 + ((((ck) ^ ((r) & 7))) << 4)))

__device__ __forceinline__ float bfu(unsigned short u) {
    return __bfloat162float(__ushort_as_bfloat16(u));
}
__device__ __forceinline__ void split2u(float v, unsigned short& hh,
                                        unsigned short& ll) {
    __nv_bfloat16 b = __float2bfloat16(v);
    hh = __bfloat16_as_ushort(b);
    ll = __bfloat16_as_ushort(__float2bfloat16(v - __bfloat162float(b)));
}

// ---------------- rope table: (cos,sin) for all (n, d2) ---------------------
__global__ void rope_table(float2* __restrict__ t) {
    int i = blockIdx.x * blockDim.x + threadIdx.x;
    if (i >= N_ * 32) return;
    int d2 = i & 31, n = i >> 5;
    float inv = powf(10000.f, -(float)d2 * (1.f / 32.f));
    float ang = (float)n * inv;
    t[i] = make_float2(cosf(ang), sinf(ang));
}

// ---------------- split fp32 -> bf16 hi/lo ----------------------------------
__global__ void split_bf16(const float* __restrict__ in,
                           __nv_bfloat16* __restrict__ hi,
                           __nv_bfloat16* __restrict__ lo, int n4) {
    int i = blockIdx.x * blockDim.x + threadIdx.x;
    if (i >= n4) return;
    float4 v = ((const float4*)in)[i];
    unsigned short h0, l0, h1, l1, h2, l2, h3, l3;
    split2u(v.x, h0, l0); split2u(v.y, h1, l1);
    split2u(v.z, h2, l2); split2u(v.w, h3, l3);
    ((ushort4*)hi)[i] = make_ushort4(h0, h1, h2, h3);
    ((ushort4*)lo)[i] = make_ushort4(l0, l1, l2, l3);
}

// ---------------- transpose + split: w[K][N] -> wt_hi/lo [N][K] --------------
__global__ void transpose_split(const float* __restrict__ w,
                                __nv_bfloat16* __restrict__ th,
                                __nv_bfloat16* __restrict__ tl, int K, int N) {
    __shared__ float t[32][33];
    int tx = threadIdx.x, ty = threadIdx.y;
    int x = blockIdx.x * 32 + tx;
#pragma unroll
    for (int j = 0; j < 32; j += 8) {
        int y = blockIdx.y * 32 + ty + j;
        t[ty + j][tx] = w[(size_t)y * N + x];
    }
    __syncthreads();
#pragma unroll
    for (int j = 0; j < 32; j += 8) {
        int n = blockIdx.x * 32 + ty + j;
        int k = blockIdx.y * 32 + tx;
        float v = t[tx][ty + j];
        __nv_bfloat16 h = __float2bfloat16(v);
        th[(size_t)n * K + k] = h;
        tl[(size_t)n * K + k] = __float2bfloat16(v - __bfloat162float(h));
    }
}

// ---------------- split-bf16 tensor-core GEMM (mma.sync, 2-stage) ------------
#define STAGE    32768
#define OFFS_AH  0
#define OFFS_AL  8192
#define OFFS_BH  16384
#define OFFS_BL  24576
#define GEMM_SMEM (2 * STAGE)

__global__ void __launch_bounds__(256, 2) mma_gemm(
    const __nv_bfloat16* __restrict__ Ah, const __nv_bfloat16* __restrict__ Al,
    const __nv_bfloat16* __restrict__ Bh, const __nv_bfloat16* __restrict__ Bl,
    float* __restrict__ C, int M, int N, int K) {
    extern __shared__ char sm[];
    const uint32_t sb = smem_u32(sm);
    const int tid = threadIdx.x;
    const int lane = tid & 31, wid = tid >> 5;
    const int warp_m = wid & 1, warp_n = wid >> 1;
    const int m0 = blockIdx.y * 128, n0 = blockIdx.x * 128;

    const int i0 = tid, i1 = tid + 256;
    const int lr0 = i0 >> 2, lc0 = i0 & 3;
    const int lr1 = i1 >> 2, lc1 = i1 & 3;
    const uint32_t so0 = swz(lr0, lc0), so1 = swz(lr1, lc1);

    uint32_t baseA[4], baseB[2];
#pragma unroll
    for (int mf = 0; mf < 4; mf++)
        baseA[mf] = swz(warp_m * 64 + mf * 16 + (lane & 15), lane >> 4);
#pragma unroll
    for (int p = 0; p < 2; p++)
        baseB[p] = swz(warp_n * 32 + p * 16 + ((lane >> 4) << 3) + (lane & 7),
                       (lane >> 3) & 1);

    float acc[4][4][4];
#pragma unroll
    for (int a = 0; a < 4; a++)
#pragma unroll
        for (int b = 0; b < 4; b++)
#pragma unroll
            for (int c = 0; c < 4; c++) acc[a][b][c] = 0.f;

    const int nIter = K >> 5;
    {
        uint32_t bs = sb;
        size_t a0 = (size_t)(m0 + lr0) * K + lc0 * 8;
        size_t a1 = (size_t)(m0 + lr1) * K + lc1 * 8;
        size_t b0 = (size_t)(n0 + lr0) * K + lc0 * 8;
        size_t b1 = (size_t)(n0 + lr1) * K + lc1 * 8;
        cp16(bs + OFFS_AH + so0, Ah + a0); cp16(bs + OFFS_AH + so1, Ah + a1);
        cp16(bs + OFFS_AL + so0, Al + a0); cp16(bs + OFFS_AL + so1, Al + a1);
        cp16(bs + OFFS_BH + so0, Bh + b0); cp16(bs + OFFS_BH + so1, Bh + b1);
        cp16(bs + OFFS_BL + so0, Bl + b0); cp16(bs + OFFS_BL + so1, Bl + b1);
        CP_COMMIT();
    }

    for (int it = 0; it < nIter; it++) {
        if (it + 1 < nIter) {
            int kk = (it + 1) << 5;
            uint32_t bs = sb + ((it + 1) & 1) * STAGE;
            size_t a0 = (size_t)(m0 + lr0) * K + kk + lc0 * 8;
            size_t a1 = (size_t)(m0 + lr1) * K + kk + lc1 * 8;
            size_t b0 = (size_t)(n0 + lr0) * K + kk + lc0 * 8;
            size_t b1 = (size_t)(n0 + lr1) * K + kk + lc1 * 8;
            cp16(bs + OFFS_AH + so0, Ah + a0); cp16(bs + OFFS_AH + so1, Ah + a1);
            cp16(bs + OFFS_AL + so0, Al + a0); cp16(bs + OFFS_AL + so1, Al + a1);
            cp16(bs + OFFS_BH + so0, Bh + b0); cp16(bs + OFFS_BH + so1, Bh + b1);
            cp16(bs + OFFS_BL + so0, Bl + b0); cp16(bs + OFFS_BL + so1, Bl + b1);
            CP_COMMIT();
            CP_WAIT(1);
        } else {
            CP_WAIT(0);
        }
        __syncthreads();

        const uint32_t ss = sb + (it & 1) * STAGE;
#pragma unroll
        for (int ks = 0; ks < 2; ks++) {
            const uint32_t kx = ks * 32;
            uint32_t bhf[4][2], blf[4][2];
#pragma unroll
            for (int p = 0; p < 2; p++) {
                uint32_t r0, r1, r2, r3;
                LDSM4(r0, r1, r2, r3, ss + OFFS_BH + (baseB[p] ^ kx));
                bhf[2 * p][0] = r0; bhf[2 * p][1] = r1;
                bhf[2 * p + 1][0] = r2; bhf[2 * p + 1][1] = r3;
                LDSM4(r0, r1, r2, r3, ss + OFFS_BL + (baseB[p] ^ kx));
                blf[2 * p][0] = r0; blf[2 * p][1] = r1;
                blf[2 * p + 1][0] = r2; blf[2 * p + 1][1] = r3;
            }
#pragma unroll
            for (int mf = 0; mf < 4; mf++) {
                uint32_t ahf[4], alf[4];
                LDSM4(ahf[0], ahf[1], ahf[2], ahf[3], ss + OFFS_AH + (baseA[mf] ^ kx));
                LDSM4(alf[0], alf[1], alf[2], alf[3], ss + OFFS_AL + (baseA[mf] ^ kx));
#pragma unroll
                for (int nf = 0; nf < 4; nf++) {
                    mma16816(acc[mf][nf], ahf, bhf[nf]);
                    mma16816(acc[mf][nf], ahf, blf[nf]);
                    mma16816(acc[mf][nf], alf, bhf[nf]);
                }
            }
        }
        __syncthreads();
    }

#pragma unroll
    for (int mf = 0; mf < 4; mf++) {
#pragma unroll
        for (int nf = 0; nf < 4; nf++) {
            int row = m0 + warp_m * 64 + mf * 16 + (lane >> 2);
            int col = n0 + warp_n * 32 + nf * 8 + 2 * (lane & 3);
            *(float2*)(C + (size_t)row * N + col) =
                make_float2(acc[mf][nf][0], acc[mf][nf][1]);
            *(float2*)(C + (size_t)(row + 8) * N + col) =
                make_float2(acc[mf][nf][2], acc[mf][nf][3]);
        }
    }
}

// ---------------- RoPE(table) + ELU feature map -> bf16 hi/lo (B,H,N,D) ------
__global__ void rope_elu(const float* __restrict__ qkv,
                         const float2* __restrict__ rt,
                         __nv_bfloat16* __restrict__ Qh, __nv_bfloat16* __restrict__ Ql,
                         __nv_bfloat16* __restrict__ Kh, __nv_bfloat16* __restrict__ Kl,
                         __nv_bfloat16* __restrict__ Vh, __nv_bfloat16* __restrict__ Vl) {
    int idx = blockIdx.x * blockDim.x + threadIdx.x;
    const int total = B_ * N_ * HEADS * 32;
    if (idx >= total) return;
    const int d2 = idx & 31;
    const int h  = (idx >> 5) & 15;
    const int n  = (idx >> 9) & 4095;
    const int b  = idx >> 21;

    size_t base = (size_t)(b * N_ + n) * (3 * DIMM);
    int c1 = h * 64 + d2;
    float q1 = qkv[base + c1],            q2 = qkv[base + c1 + 32];
    float k1 = qkv[base + 1024 + c1],     k2 = qkv[base + 1024 + c1 + 32];
    float v1 = qkv[base + 2048 + c1],     v2 = qkv[base + 2048 + c1 + 32];

    float2 csn = rt[n * 32 + d2];
    float cs = csn.x, sn = csn.y;
    float qr1 = q1 * cs - q2 * sn, qr2 = q1 * sn + q2 * cs;
    float kr1 = k1 * cs - k2 * sn, kr2 = k1 * sn + k2 * cs;

    const float SC = 0.35355339059327373f;
    float y;
    y = qr1 * SC; float fq1 = (y > 0.f) ? y + 1.f : __expf(y);
    y = qr2 * SC; float fq2 = (y > 0.f) ? y + 1.f : __expf(y);
    y = kr1 * SC; float fk1 = (y > 0.f) ? y + 1.f : __expf(y);
    y = kr2 * SC; float fk2 = (y > 0.f) ? y + 1.f : __expf(y);

    size_t ob = ((size_t)((b * HEADS + h)) * N_ + n) * HD;
    unsigned short hh, ll;
    split2u(fq1, hh, ll);
    ((unsigned short*)Qh)[ob + d2] = hh;      ((unsigned short*)Ql)[ob + d2] = ll;
    split2u(fq2, hh, ll);
    ((unsigned short*)Qh)[ob + d2 + 32] = hh; ((unsigned short*)Ql)[ob + d2 + 32] = ll;
    split2u(fk1, hh, ll);
    ((unsigned short*)Kh)[ob + d2] = hh;      ((unsigned short*)Kl)[ob + d2] = ll;
    split2u(fk2, hh, ll);
    ((unsigned short*)Kh)[ob + d2 + 32] = hh; ((unsigned short*)Kl)[ob + d2 + 32] = ll;
    split2u(v1, hh, ll);
    ((unsigned short*)Vh)[ob + d2] = hh;      ((unsigned short*)Vl)[ob + d2] = ll;
    split2u(v2, hh, ll);
    ((unsigned short*)Vh)[ob + d2 + 32] = hh; ((unsigned short*)Vl)[ob + d2 + 32] = ll;
}

// ---------------- mma-based chunked linear attention, m-split x2 -------------
#define T_QH 0
#define T_QL 8192
#define T_KH 16384
#define T_KL 24576
#define T_VH 32768                 // 64x32 half tile (64B rows), 4096 B
#define T_VL 36864
#define BUFSZ 40960
#define O_KTH (2*BUFSZ)            // 81920  (64x64 SWZ64)
#define O_KTL (O_KTH + 8192)
#define O_VTH (O_KTL + 8192)       // 98304  (32x64 SWZ64, 4096 B)
#define O_VTL (O_VTH + 4096)
#define O_SH  (O_VTL + 4096)       // 106496 (64x64 SWZ64)
#define O_SL  (O_SH + 8192)
#define O_KVH (O_SL + 8192)        // 122880 (32x64 SWZ64, 4096 B)
#define O_KVL (O_KVH + 4096)
#define O_KVF (O_KVL + 4096)       // 131072 (fp32 32x64 = 8192 B)
#define O_KS  (O_KVF + 8192)       // 139264
#define O_DEN (O_KS + 256)
#define O_DENP (O_DEN + 256)
#define LA_SMEM (O_DENP + 1024)    // 140800

__device__ __forceinline__ void mm64(uint32_t aHt, uint32_t aLt,
                                     uint32_t bHt, uint32_t bLt,
                                     float (*acc)[2][4], int wm, int wn, int lane) {
    const uint32_t aOff0 = SWZ64(wm * 32 + (lane & 15), (lane >> 4));
    const uint32_t aOff1 = SWZ64(wm * 32 + 16 + (lane & 15), (lane >> 4));
    const uint32_t bOff  = SWZ64(wn * 16 + ((lane >> 4) << 3) + (lane & 7),
                                 (lane >> 3) & 1);
#pragma unroll
    for (int kx = 0; kx < 4; kx++) {
        const uint32_t x = kx << 5;
        uint32_t BH[2][2], BL[2][2], r0, r1, r2, r3;
        LDSM4(r0, r1, r2, r3, bHt + (bOff ^ x));
        BH[0][0] = r0; BH[0][1] = r1; BH[1][0] = r2; BH[1][1] = r3;
        LDSM4(r0, r1, r2, r3, bLt + (bOff ^ x));
        BL[0][0] = r0; BL[0][1] = r1; BL[1][0] = r2; BL[1][1] = r3;
#pragma unroll
        for (int mf = 0; mf < 2; mf++) {
            uint32_t ao = (mf ? aOff1 : aOff0) ^ x;
            uint32_t AH[4], AL[4];
            LDSM4(AH[0], AH[1], AH[2], AH[3], aHt + ao);
            LDSM4(AL[0], AL[1], AL[2], AL[3], aLt + ao);
#pragma unroll
            for (int nf = 0; nf < 2; nf++) {
                mma16816(acc[mf][nf], AH, BH[nf]);
                mma16816(acc[mf][nf], AH, BL[nf]);
                mma16816(acc[mf][nf], AL, BH[nf]);
            }
        }
    }
}

__device__ __forceinline__ void mm16(uint32_t aHt, uint32_t aLt,
                                     uint32_t bHt, uint32_t bLt,
                                     float (*acc)[4], int ar, int bc, int lane) {
    const uint32_t aOff = SWZ64(ar + (lane & 15), (lane >> 4));
    const uint32_t bOff = SWZ64(bc + ((lane >> 4) << 3) + (lane & 7),
                                (lane >> 3) & 1);
#pragma unroll
    for (int kx = 0; kx < 4; kx++) {
        const uint32_t x = kx << 5;
        uint32_t BH[2][2], BL[2][2], r0, r1, r2, r3;
        LDSM4(r0, r1, r2, r3, bHt + (bOff ^ x));
        BH[0][0] = r0; BH[0][1] = r1; BH[1][0] = r2; BH[1][1] = r3;
        LDSM4(r0, r1, r2, r3, bLt + (bOff ^ x));
        BL[0][0] = r0; BL[0][1] = r1; BL[1][0] = r2; BL[1][1] = r3;
        uint32_t AH[4], AL[4];
        LDSM4(AH[0], AH[1], AH[2], AH[3], aHt + (aOff ^ x));
        LDSM4(AL[0], AL[1], AL[2], AL[3], aLt + (aOff ^ x));
#pragma unroll
        for (int nf = 0; nf < 2; nf++) {
            mma16816(acc[nf], AH, BH[nf]);
            mma16816(acc[nf], AH, BL[nf]);
            mma16816(acc[nf], AL, BH[nf]);
        }
    }
}

__device__ __forceinline__ void load_tile64(uint32_t dst,
                                            const __nv_bfloat16* g,
                                            size_t rowbase, int tid) {
#pragma unroll
    for (int uu = 0; uu < 2; uu++) {
        int u = tid + uu * 256;
        int r = u >> 3, ck = u & 7;
        cp16(dst + SWZ64(r, ck), g + rowbase + r * 64 + ck * 8);
    }
}
__device__ __forceinline__ void load_vhalf(uint32_t dst,
                                           const __nv_bfloat16* g,
                                           size_t rowbase, int mh, int tid) {
    int r = tid >> 2, ck = tid & 3;
    cp16(dst + swz(r, ck), g + rowbase + r * 64 + mh * 32 + ck * 8);
}

__global__ void __launch_bounds__(256) linattn_mma(
    const __nv_bfloat16* __restrict__ Qh, const __nv_bfloat16* __restrict__ Ql,
    const __nv_bfloat16* __restrict__ Kh, const __nv_bfloat16* __restrict__ Kl,
    const __nv_bfloat16* __restrict__ Vh, const __nv_bfloat16* __restrict__ Vl,
    __nv_bfloat16* __restrict__ ah, __nv_bfloat16* __restrict__ al) {
    extern __shared__ __align__(128) char smx[];
    const uint32_t sb = smem_u32(smx);
    const int tid = threadIdx.x;
    const int lane = tid & 31, wid = tid >> 5;
    const int wm = wid & 1, wn = wid >> 1;          // P1 geometry (2x4)
    const int wr3 = (wid & 3) * 16, wc3 = (wid >> 2) * 16;  // P3: 64x32
    const int wr4 = (wid & 1) * 16, wc4 = (wid >> 1) * 16;  // P4: 32x64
    const int bh = blockIdx.x >> 1;
    const int mh = blockIdx.x & 1;
    const int bIdx = bh >> 4, hIdx = bh & 15;
    const size_t gb = (size_t)bh * N_ * HD;

    float* ksp  = (float*)(smx + O_KS);
    float* denp = (float*)(smx + O_DENP);
    float* denv = (float*)(smx + O_DEN);
    float* kvf  = (float*)(smx + O_KVF);

    for (int i = tid; i < 2048; i += 256) {
        kvf[i] = 0.f;
        *(unsigned short*)(smx + O_KVH + i * 2) = 0;
        *(unsigned short*)(smx + O_KVL + i * 2) = 0;
    }
    if (tid < 64) ksp[tid] = 0.f;

    load_tile64(sb + T_QH, Qh, gb, tid);
    load_tile64(sb + T_QL, Ql, gb, tid);
    load_tile64(sb + T_KH, Kh, gb, tid);
    load_tile64(sb + T_KL, Kl, gb, tid);
    load_vhalf(sb + T_VH, Vh, gb, mh, tid);
    load_vhalf(sb + T_VL, Vl, gb, mh, tid);
    CP_COMMIT();
    __syncthreads();

    for (int ch = 0; ch < 64; ch++) {
        const int n0 = ch * 64;
        const uint32_t bo = (ch & 1) * BUFSZ;
        CP_WAIT(0);
        __syncthreads();

        for (int idx = tid; idx < 4096; idx += 256) {
            int i = idx >> 6, d = idx & 63;
            uint32_t ro = SWZ64(i, d >> 3) + (d & 7) * 2;
            uint32_t wo = SWZ64(d, i >> 3) + (i & 7) * 2;
            *(unsigned short*)(smx + O_KTH + wo) = *(unsigned short*)(smx + bo + T_KH + ro);
            *(unsigned short*)(smx + O_KTL + wo) = *(unsigned short*)(smx + bo + T_KL + ro);
        }
        for (int idx = tid; idx < 2048; idx += 256) {
            int m = idx >> 6, i = idx & 63;
            uint32_t ro = swz(i, m >> 3) + (m & 7) * 2;
            uint32_t wo = SWZ64(m, i >> 3) + (i & 7) * 2;
            *(unsigned short*)(smx + O_VTH + wo) = *(unsigned short*)(smx + bo + T_VH + ro);
            *(unsigned short*)(smx + O_VTL + wo) = *(unsigned short*)(smx + bo + T_VL + ro);
        }
        if (ch + 1 < 64) {
            const uint32_t bo2 = ((ch + 1) & 1) * BUFSZ;
            size_t rb = gb + (size_t)(n0 + 64) * HD;
            load_tile64(sb + bo2 + T_QH, Qh, rb, tid);
            load_tile64(sb + bo2 + T_QL, Ql, rb, tid);
            load_tile64(sb + bo2 + T_KH, Kh, rb, tid);
            load_tile64(sb + bo2 + T_KL, Kl, rb, tid);
            load_vhalf(sb + bo2 + T_VH, Vh, rb, mh, tid);
            load_vhalf(sb + bo2 + T_VL, Vl, rb, mh, tid);
            CP_COMMIT();
        }
        __syncthreads();

        // ---- P1: S = Q K^T, mask, rowsums, split to smem ----
        {
            float accS[2][2][4];
#pragma unroll
            for (int a = 0; a < 2; a++)
#pragma unroll
                for (int b = 0; b < 2; b++)
#pragma unroll
                    for (int e = 0; e < 4; e++) accS[a][b][e] = 0.f;
            mm64(sb + bo + T_QH, sb + bo + T_QL, sb + bo + T_KH, sb + bo + T_KL,
                 accS, wm, wn, lane);
#pragma unroll
            for (int mf = 0; mf < 2; mf++) {
                int r0 = wm * 32 + mf * 16 + (lane >> 2), r1 = r0 + 8;
                float rs0 = 0.f, rs1 = 0.f;
#pragma unroll
                for (int nf = 0; nf < 2; nf++) {
                    int cc = wn * 16 + nf * 8 + 2 * (lane & 3);
                    float a0 = (cc     <= r0) ? accS[mf][nf][0] : 0.f;
                    float a1 = (cc + 1 <= r0) ? accS[mf][nf][1] : 0.f;
                    float a2 = (cc     <= r1) ? accS[mf][nf][2] : 0.f;
                    float a3 = (cc + 1 <= r1) ? accS[mf][nf][3] : 0.f;
                    rs0 += a0 + a1; rs1 += a2 + a3;
                    unsigned short h0, l0, h1, l1;
                    split2u(a0, h0, l0); split2u(a1, h1, l1);
                    uint32_t so = SWZ64(r0, cc >> 3) + (cc & 7) * 2;
                    *(ushort2*)(smx + O_SH + so) = make_ushort2(h0, h1);
                    *(ushort2*)(smx + O_SL + so) = make_ushort2(l0, l1);
                    split2u(a2, h0, l0); split2u(a3, h1, l1);
                    so = SWZ64(r1, cc >> 3) + (cc & 7) * 2;
                    *(ushort2*)(smx + O_SH + so) = make_ushort2(h0, h1);
                    *(ushort2*)(smx + O_SL + so) = make_ushort2(l0, l1);
                }
                rs0 += __shfl_xor_sync(0xffffffffu, rs0, 1);
                rs0 += __shfl_xor_sync(0xffffffffu, rs0, 2);
                rs1 += __shfl_xor_sync(0xffffffffu, rs1, 1);
                rs1 += __shfl_xor_sync(0xffffffffu, rs1, 2);
                if ((lane & 3) == 0) {
                    denp[wn * 64 + r0] = rs0;
                    denp[wn * 64 + r1] = rs1;
                }
            }
        }
        __syncthreads();

        // ---- P2: den ----
        if (tid < 64) {
            int i = tid;
            float s = denp[i] + denp[64 + i] + denp[128 + i] + denp[192 + i];
            for (int d = 0; d < 64; d++) {
                uint32_t qo = SWZ64(i, d >> 3) + (d & 7) * 2;
                float qv = bfu(*(unsigned short*)(smx + bo + T_QH + qo)) +
                           bfu(*(unsigned short*)(smx + bo + T_QL + qo));
                s += qv * ksp[d];
            }
            denv[i] = fmaxf(s, 1e-6f);
        }
        __syncthreads();

        // ---- P3: O(64x32) ----
        {
            float accO[2][4];
#pragma unroll
            for (int b = 0; b < 2; b++)
#pragma unroll
                for (int e = 0; e < 4; e++) accO[b][e] = 0.f;
            mm16(sb + bo + T_QH, sb + bo + T_QL, sb + O_KVH, sb + O_KVL,
                 accO, wr3, wc3, lane);
            mm16(sb + O_SH, sb + O_SL, sb + O_VTH, sb + O_VTL,
                 accO, wr3, wc3, lane);
            int r0 = wr3 + (lane >> 2), r1 = r0 + 8;
            float i0 = 1.f / denv[r0], i1 = 1.f / denv[r1];
#pragma unroll
            for (int nf = 0; nf < 2; nf++) {
                int cc = wc3 + nf * 8 + 2 * (lane & 3);
                unsigned short h0, l0, h1, l1;
                size_t ro = (size_t)(bIdx * N_ + n0 + r0) * DIMM + hIdx * 64 +
                            mh * 32 + cc;
                split2u(accO[nf][0] * i0, h0, l0);
                split2u(accO[nf][1] * i0, h1, l1);
                *(ushort2*)((unsigned short*)ah + ro) = make_ushort2(h0, h1);
                *(ushort2*)((unsigned short*)al + ro) = make_ushort2(l0, l1);
                ro = (size_t)(bIdx * N_ + n0 + r1) * DIMM + hIdx * 64 +
                     mh * 32 + cc;
                split2u(accO[nf][2] * i1, h0, l0);
                split2u(accO[nf][3] * i1, h1, l1);
                *(ushort2*)((unsigned short*)ah + ro) = make_ushort2(h0, h1);
                *(ushort2*)((unsigned short*)al + ro) = make_ushort2(l0, l1);
            }
        }

        // ---- P4: KVt += V^T K ----
        {
            float accU[2][4];
#pragma unroll
            for (int b = 0; b < 2; b++)
#pragma unroll
                for (int e = 0; e < 4; e++) accU[b][e] = 0.f;
            mm16(sb + O_VTH, sb + O_VTL, sb + O_KTH, sb + O_KTL,
                 accU, wr4, wc4, lane);
            int m0r = wr4 + (lane >> 2), m1r = m0r + 8;
#pragma unroll
            for (int nf = 0; nf < 2; nf++) {
                int dd = wc4 + nf * 8 + 2 * (lane & 3);
                kvf[m0r * 64 + dd]     += accU[nf][0];
                kvf[m0r * 64 + dd + 1] += accU[nf][1];
                kvf[m1r * 64 + dd]     += accU[nf][2];
                kvf[m1r * 64 + dd + 1] += accU[nf][3];
            }
        }
        __syncthreads();
        for (int idx = tid; idx < 2048; idx += 256) {
            int m = idx >> 6, d = idx & 63;
            unsigned short hh, ll;
            split2u(kvf[idx], hh, ll);
            uint32_t o = SWZ64(m, d >> 3) + (d & 7) * 2;
            *(unsigned short*)(smx + O_KVH + o) = hh;
            *(unsigned short*)(smx + O_KVL + o) = ll;
        }
        if (tid < 64) {
            int d = tid;
            float s = ksp[d];
            for (int i2 = 0; i2 < 64; i2++) {
                uint32_t o = SWZ64(d, i2 >> 3) + (i2 & 7) * 2;
                s += bfu(*(unsigned short*)(smx + O_KTH + o)) +
                     bfu(*(unsigned short*)(smx + O_KTL + o));
            }
            ksp[d] = s;
        }
        __syncthreads();
    }
}

// ---------------- launch -----------------------------------------------------
extern "C" void kernel_launch(void* const* d_in, const int* in_sizes, int n_in,
                              void* d_out, int out_size) {
    const float* x    = (const float*)d_in[0];
    const float* wqkv = (const float*)d_in[1];
    const float* wout = (const float*)d_in[2];
    float* out = (float*)d_out;

    float* qkv;
    __nv_bfloat16 *Qh, *Ql, *Kh, *Kl, *Vh, *Vl;
    __nv_bfloat16 *xh, *xl, *ah, *al, *wqh, *wql, *woh, *wol;
    float2* rt;
    cudaGetSymbolAddress((void**)&qkv, g_qkv);
    cudaGetSymbolAddress((void**)&Qh,  g_Qh);
    cudaGetSymbolAddress((void**)&Ql,  g_Ql);
    cudaGetSymbolAddress((void**)&Kh,  g_Kh);
    cudaGetSymbolAddress((void**)&Kl,  g_Kl);
    cudaGetSymbolAddress((void**)&Vh,  g_Vh);
    cudaGetSymbolAddress((void**)&Vl,  g_Vl);
    cudaGetSymbolAddress((void**)&xh,  g_xh);
    cudaGetSymbolAddress((void**)&xl,  g_xl);
    cudaGetSymbolAddress((void**)&ah,  g_ah);
    cudaGetSymbolAddress((void**)&al,  g_al);
    cudaGetSymbolAddress((void**)&wqh, g_wqh);
    cudaGetSymbolAddress((void**)&wql, g_wql);
    cudaGetSymbolAddress((void**)&woh, g_woh);
    cudaGetSymbolAddress((void**)&wol, g_wol);
    cudaGetSymbolAddress((void**)&rt,  g_rope);

    cudaFuncSetAttribute(mma_gemm, cudaFuncAttributeMaxDynamicSharedMemorySize,
                         GEMM_SMEM);
    cudaFuncSetAttribute(linattn_mma, cudaFuncAttributeMaxDynamicSharedMemorySize,
                         LA_SMEM);

    // rope table; split x; transpose+split weights
    {
        rope_table<<<(N_ * 32 + 255) / 256, 256>>>(rt);
        int n4 = ROWS * DIMM / 4;
        split_bf16<<<(n4 + 255) / 256, 256>>>(x, xh, xl, n4);
        transpose_split<<<dim3(3 * DIMM / 32, DIMM / 32), dim3(32, 8)>>>(
            wqkv, wqh, wql, DIMM, 3 * DIMM);
        transpose_split<<<dim3(DIMM / 32, DIMM / 32), dim3(32, 8)>>>(
            wout, woh, wol, DIMM, DIMM);
    }
    // 1) qkv = x @ w_qkv   (tensor cores, 2-stage pipeline)
    mma_gemm<<<dim3(3 * DIMM / 128, ROWS / 128), 256, GEMM_SMEM>>>(
        xh, xl, wqh, wql, qkv, ROWS, 3 * DIMM, DIMM);
    // 2) RoPE(table) + ELU -> bf16 hi/lo features
    {
        int total = B_ * N_ * HEADS * 32;
        rope_elu<<<(total + 255) / 256, 256>>>(qkv, rt, Qh, Ql, Kh, Kl, Vh, Vl);
    }
    // 3) tensor-core chunked linear attention, m-split x2
    linattn_mma<<<NBH * 2, 256, LA_SMEM>>>(Qh, Ql, Kh, Kl, Vh, Vl, ah, al);
    // 4) out = attn @ w_out
    mma_gemm<<<dim3(DIMM / 128, ROWS / 128), 256, GEMM_SMEM>>>(
        ah, al, woh, wol, out, ROWS, DIMM, DIMM);
}